// round 5
// baseline (speedup 1.0000x reference)
#include <cuda_runtime.h>
#include <cuda_bf16.h>
#include <cstdint>

// Problem constants
#define T_LEN   4096
#define D_DIM   64
#define R_OUT   127
#define HALF_W  63

#define TT      128      // t rows per tile (M)
#define NS      256      // k halo rows staged (N); rows 254..255 zero
#define SROWS   254

// SMEM layout (bf16 tiles, 128 B per row, SW128-style 16B swizzle)
#define SM_A_HI   0
#define SM_A_LO   (SM_A_HI + TT * 128)      // 16384
#define SM_B_HI   (SM_A_LO + TT * 128)      // 32768
#define SM_B_LO   (SM_B_HI + NS * 128)      // 65536
#define SM_TOTAL  (SM_B_LO + NS * 128)      // 98304

#define SWZ(off) ((off) ^ (((off) >> 3) & 0x70))

static __device__ __forceinline__ uint32_t smem_u32(const void* p) {
    uint32_t a;
    asm("{ .reg .u64 t; cvta.to.shared.u64 t, %1; cvt.u32.u64 %0, t; }" : "=r"(a) : "l"(p));
    return a;
}

// fp32x4 -> packed bf16x2 hi pair + residual lo pair
static __device__ __forceinline__ void split4(float4 v, uint32_t& h0, uint32_t& h1,
                                              uint32_t& l0, uint32_t& l1) {
    asm("cvt.rn.bf16x2.f32 %0, %1, %2;" : "=r"(h0) : "f"(v.y), "f"(v.x));
    asm("cvt.rn.bf16x2.f32 %0, %1, %2;" : "=r"(h1) : "f"(v.w), "f"(v.z));
    float rx = v.x - __uint_as_float(h0 << 16);
    float ry = v.y - __uint_as_float(h0 & 0xffff0000u);
    float rz = v.z - __uint_as_float(h1 << 16);
    float rw = v.w - __uint_as_float(h1 & 0xffff0000u);
    asm("cvt.rn.bf16x2.f32 %0, %1, %2;" : "=r"(l0) : "f"(ry), "f"(rx));
    asm("cvt.rn.bf16x2.f32 %0, %1, %2;" : "=r"(l1) : "f"(rw), "f"(rz));
}

#define LDSM_X4(r0, r1, r2, r3, a) \
    asm volatile("ldmatrix.sync.aligned.m8n8.x4.shared.b16 {%0,%1,%2,%3}, [%4];" \
        : "=r"(r0), "=r"(r1), "=r"(r2), "=r"(r3) : "r"(a))

#define MMA16816(d, a0, a1, a2, a3, b0, b1) \
    asm volatile("mma.sync.aligned.m16n8k16.row.col.f32.bf16.bf16.f32 " \
        "{%0,%1,%2,%3}, {%4,%5,%6,%7}, {%8,%9}, {%0,%1,%2,%3};" \
        : "+f"(d[0]), "+f"(d[1]), "+f"(d[2]), "+f"(d[3]) \
        : "r"(a0), "r"(a1), "r"(a2), "r"(a3), "r"(b0), "r"(b1))

__global__ void __launch_bounds__(256, 2)
unfold_dot_hmma(const float* __restrict__ q,
                const float* __restrict__ k,
                float* __restrict__ out)
{
    extern __shared__ char smem[];
    const uint32_t sb = smem_u32(smem);
    const int tid = threadIdx.x;
    const int wid = tid >> 5;
    const int lid = tid & 31;
    const int t0  = blockIdx.x * TT;
    const int bh  = blockIdx.y;

    // ---- stage Q tile: 128 rows x 64 d -> bf16 hi/lo, swizzled rows of 128B ----
    const float4* qg = reinterpret_cast<const float4*>(q) +
                       ((size_t)bh * T_LEN + t0) * (D_DIM / 4);
    #pragma unroll
    for (int it = 0; it < 4; ++it) {
        int idx = tid + it * 256;          // 0..1023
        int row = idx >> 3;
        int g   = idx & 7;                 // 16B chunk within row
        float4 v0 = qg[row * 16 + g * 2];
        float4 v1 = qg[row * 16 + g * 2 + 1];
        uint32_t h0, h1, h2, h3, l0, l1, l2, l3;
        split4(v0, h0, h1, l0, l1);
        split4(v1, h2, h3, l2, l3);
        uint32_t off = SWZ((uint32_t)(row * 128 + g * 16));
        *reinterpret_cast<uint4*>(smem + SM_A_HI + off) = make_uint4(h0, h1, h2, h3);
        *reinterpret_cast<uint4*>(smem + SM_A_LO + off) = make_uint4(l0, l1, l2, l3);
    }

    // ---- stage K halo: 256 rows (s = t0-63+srow), zero outside [0,T) ----
    const float4* kg = reinterpret_cast<const float4*>(k) +
                       (size_t)bh * T_LEN * (D_DIM / 4);
    #pragma unroll
    for (int it = 0; it < 8; ++it) {
        int idx  = tid + it * 256;         // 0..2047
        int srow = idx >> 3;
        int g    = idx & 7;
        int sg   = t0 - HALF_W + srow;
        float4 v0 = make_float4(0.f, 0.f, 0.f, 0.f);
        float4 v1 = v0;
        if (srow < SROWS && (unsigned)sg < T_LEN) {
            v0 = kg[sg * 16 + g * 2];
            v1 = kg[sg * 16 + g * 2 + 1];
        }
        uint32_t h0, h1, h2, h3, l0, l1, l2, l3;
        split4(v0, h0, h1, l0, l1);
        split4(v1, h2, h3, l2, l3);
        uint32_t off = SWZ((uint32_t)(srow * 128 + g * 16));
        *reinterpret_cast<uint4*>(smem + SM_B_HI + off) = make_uint4(h0, h1, h2, h3);
        *reinterpret_cast<uint4*>(smem + SM_B_LO + off) = make_uint4(l0, l1, l2, l3);
    }
    __syncthreads();

    // ---- compute: warp w owns rows [16w,16w+16), band col tiles j=0..17 at n0=m0+8j
    const int m0 = wid * 16;

    float acc[18][4];
    #pragma unroll
    for (int j = 0; j < 18; ++j)
        #pragma unroll
        for (int e = 0; e < 4; ++e) acc[j][e] = 0.f;

    // A lane address (ldmatrix x4: m0=r0-7/k0-7, m1=r8-15/k0-7, m2=r0-7/k8-15, m3=r8-15/k8-15)
    const int amat = lid >> 3;
    const uint32_t a_base = (uint32_t)((m0 + (amat & 1) * 8 + (lid & 7)) * 128
                                       + (amat >> 1) * 16);
    // B lane address (x4 over two adjacent n8 tiles)
    const int bg = lid >> 3;
    const uint32_t b_base = (uint32_t)((m0 + (bg >> 1) * 8 + (lid & 7)) * 128
                                       + (bg & 1) * 16);

    #pragma unroll
    for (int kc = 0; kc < 4; ++kc) {
        uint32_t ah0, ah1, ah2, ah3, al0, al1, al2, al3;
        uint32_t aoff = SWZ(a_base + kc * 32);
        LDSM_X4(ah0, ah1, ah2, ah3, sb + SM_A_HI + aoff);
        LDSM_X4(al0, al1, al2, al3, sb + SM_A_LO + aoff);

        uint32_t boff = SWZ(b_base + kc * 32);    // jp steps add 2048: swizzle-invariant
        #pragma unroll
        for (int jp = 0; jp < 9; ++jp) {
            uint32_t bh0, bh1, bh2, bh3, bl0, bl1, bl2, bl3;
            LDSM_X4(bh0, bh1, bh2, bh3, sb + SM_B_HI + boff);
            LDSM_X4(bl0, bl1, bl2, bl3, sb + SM_B_LO + boff);
            // interleave the two acc chains (dep distance 2, not 3-deep RAW)
            MMA16816(acc[2 * jp    ], ah0, ah1, ah2, ah3, bh0, bh1);
            MMA16816(acc[2 * jp + 1], ah0, ah1, ah2, ah3, bh2, bh3);
            MMA16816(acc[2 * jp    ], ah0, ah1, ah2, ah3, bl0, bl1);
            MMA16816(acc[2 * jp + 1], ah0, ah1, ah2, ah3, bl2, bl3);
            MMA16816(acc[2 * jp    ], al0, al1, al2, al3, bh0, bh1);
            MMA16816(acc[2 * jp + 1], al0, al1, al2, al3, bh2, bh3);
            boff += 16 * 128;
        }
    }

    // ---- epilogue: direct streaming stores of the band to global ----
    // D frag: {d0,d1}=D[l/4][(l%4)*2 +0/1], {d2,d3}=D[l/4+8][same]
    // out[t0+i, rr] at op[i*127 + rr], rr = col - i  ->  op[i*126 + col]
    {
        float* op = out + ((size_t)bh * T_LEN + t0) * R_OUT;
        const int r0 = m0 + (lid >> 2);
        const int c0 = (lid & 3) * 2;
        #pragma unroll
        for (int j = 0; j < 18; ++j) {
            int n0 = m0 + j * 8;
            #pragma unroll
            for (int e = 0; e < 4; ++e) {
                int i   = r0 + ((e >> 1) << 3);
                int col = n0 + c0 + (e & 1);
                unsigned rr = (unsigned)(col - i);
                if (rr < R_OUT)
                    __stcs(op + i * (R_OUT - 1) + col, acc[j][e]);
            }
        }
    }
}

extern "C" void kernel_launch(void* const* d_in, const int* in_sizes, int n_in,
                              void* d_out, int out_size)
{
    const float* q = (const float*)d_in[0];
    const float* k = (const float*)d_in[1];
    float* out     = (float*)d_out;

    int bh = in_sizes[0] / (T_LEN * D_DIM);   // 128

    cudaFuncSetAttribute(unfold_dot_hmma,
                         cudaFuncAttributeMaxDynamicSharedMemorySize, SM_TOTAL);

    dim3 grid(T_LEN / TT, bh);
    unfold_dot_hmma<<<grid, 256, SM_TOTAL>>>(q, k, out);
}

// round 6
// speedup vs baseline: 1.3259x; 1.3259x over previous
#include <cuda_runtime.h>
#include <cuda_bf16.h>
#include <cstdint>

// Problem constants
#define T_LEN   4096
#define D_DIM   64
#define R_OUT   127
#define HALF_W  63

#define TT      128      // t rows per tile (M)
#define NS      256      // k halo rows staged (N); rows 254..255 zero
#define SROWS   254

// SMEM layout (bf16 tiles, 128 B per row, SW128-style 16B swizzle)
#define SM_A_HI   0
#define SM_A_LO   (SM_A_HI + TT * 128)      // 16384
#define SM_B_HI   (SM_A_LO + TT * 128)      // 32768
#define SM_B_LO   (SM_B_HI + NS * 128)      // 65536
#define SM_TOTAL  (SM_B_LO + NS * 128)      // 98304
#define SM_BAND   SM_B_HI                    // aliased over B after compute (65024 B)

#define SWZ(off) ((off) ^ (((off) >> 3) & 0x70))

static __device__ __forceinline__ uint32_t smem_u32(const void* p) {
    uint32_t a;
    asm("{ .reg .u64 t; cvta.to.shared.u64 t, %1; cvt.u32.u64 %0, t; }" : "=r"(a) : "l"(p));
    return a;
}

// fp32x4 -> packed bf16x2 hi pair + residual lo pair
static __device__ __forceinline__ void split4(float4 v, uint32_t& h0, uint32_t& h1,
                                              uint32_t& l0, uint32_t& l1) {
    asm("cvt.rn.bf16x2.f32 %0, %1, %2;" : "=r"(h0) : "f"(v.y), "f"(v.x));
    asm("cvt.rn.bf16x2.f32 %0, %1, %2;" : "=r"(h1) : "f"(v.w), "f"(v.z));
    float rx = v.x - __uint_as_float(h0 << 16);
    float ry = v.y - __uint_as_float(h0 & 0xffff0000u);
    float rz = v.z - __uint_as_float(h1 << 16);
    float rw = v.w - __uint_as_float(h1 & 0xffff0000u);
    asm("cvt.rn.bf16x2.f32 %0, %1, %2;" : "=r"(l0) : "f"(ry), "f"(rx));
    asm("cvt.rn.bf16x2.f32 %0, %1, %2;" : "=r"(l1) : "f"(rw), "f"(rz));
}

#define LDSM_X4(r0, r1, r2, r3, a) \
    asm volatile("ldmatrix.sync.aligned.m8n8.x4.shared.b16 {%0,%1,%2,%3}, [%4];" \
        : "=r"(r0), "=r"(r1), "=r"(r2), "=r"(r3) : "r"(a))

#define MMA16816(d, a0, a1, a2, a3, b0, b1) \
    asm volatile("mma.sync.aligned.m16n8k16.row.col.f32.bf16.bf16.f32 " \
        "{%0,%1,%2,%3}, {%4,%5,%6,%7}, {%8,%9}, {%0,%1,%2,%3};" \
        : "+f"(d[0]), "+f"(d[1]), "+f"(d[2]), "+f"(d[3]) \
        : "r"(a0), "r"(a1), "r"(a2), "r"(a3), "r"(b0), "r"(b1))

__global__ void __launch_bounds__(256, 2)
unfold_dot_hmma(const float* __restrict__ q,
                const float* __restrict__ k,
                float* __restrict__ out)
{
    extern __shared__ char smem[];
    const uint32_t sb = smem_u32(smem);
    const int tid = threadIdx.x;
    const int wid = tid >> 5;
    const int lid = tid & 31;
    const int t0  = blockIdx.x * TT;
    const int bh  = blockIdx.y;

    // ---- stage Q tile: 128 rows x 64 d -> bf16 hi/lo, swizzled rows of 128B ----
    const float4* qg = reinterpret_cast<const float4*>(q) +
                       ((size_t)bh * T_LEN + t0) * (D_DIM / 4);
    #pragma unroll
    for (int it = 0; it < 4; ++it) {
        int idx = tid + it * 256;          // 0..1023
        int row = idx >> 3;
        int g   = idx & 7;                 // 16B chunk within row
        float4 v0 = qg[row * 16 + g * 2];
        float4 v1 = qg[row * 16 + g * 2 + 1];
        uint32_t h0, h1, h2, h3, l0, l1, l2, l3;
        split4(v0, h0, h1, l0, l1);
        split4(v1, h2, h3, l2, l3);
        uint32_t off = SWZ((uint32_t)(row * 128 + g * 16));
        *reinterpret_cast<uint4*>(smem + SM_A_HI + off) = make_uint4(h0, h1, h2, h3);
        *reinterpret_cast<uint4*>(smem + SM_A_LO + off) = make_uint4(l0, l1, l2, l3);
    }

    // ---- stage K halo: 256 rows (s = t0-63+srow), zero outside [0,T) ----
    const float4* kg = reinterpret_cast<const float4*>(k) +
                       (size_t)bh * T_LEN * (D_DIM / 4);
    #pragma unroll
    for (int it = 0; it < 8; ++it) {
        int idx  = tid + it * 256;         // 0..2047
        int srow = idx >> 3;
        int g    = idx & 7;
        int sg   = t0 - HALF_W + srow;
        float4 v0 = make_float4(0.f, 0.f, 0.f, 0.f);
        float4 v1 = v0;
        if (srow < SROWS && (unsigned)sg < T_LEN) {
            v0 = kg[sg * 16 + g * 2];
            v1 = kg[sg * 16 + g * 2 + 1];
        }
        uint32_t h0, h1, h2, h3, l0, l1, l2, l3;
        split4(v0, h0, h1, l0, l1);
        split4(v1, h2, h3, l2, l3);
        uint32_t off = SWZ((uint32_t)(srow * 128 + g * 16));
        *reinterpret_cast<uint4*>(smem + SM_B_HI + off) = make_uint4(h0, h1, h2, h3);
        *reinterpret_cast<uint4*>(smem + SM_B_LO + off) = make_uint4(l0, l1, l2, l3);
    }
    __syncthreads();

    // ---- compute: warp w owns rows [16w,16w+16), band col tiles j=0..17 at n0=m0+8j
    const int m0 = wid * 16;

    float acc[18][4];
    #pragma unroll
    for (int j = 0; j < 18; ++j)
        #pragma unroll
        for (int e = 0; e < 4; ++e) acc[j][e] = 0.f;

    // A lane address (ldmatrix x4)
    const int amat = lid >> 3;
    const uint32_t a_base = (uint32_t)((m0 + (amat & 1) * 8 + (lid & 7)) * 128
                                       + (amat >> 1) * 16);
    // B lane address (x4 over two adjacent n8 tiles)
    const int bg = lid >> 3;
    const uint32_t b_base = (uint32_t)((m0 + (bg >> 1) * 8 + (lid & 7)) * 128
                                       + (bg & 1) * 16);

    #pragma unroll
    for (int kc = 0; kc < 4; ++kc) {
        uint32_t ah0, ah1, ah2, ah3, al0, al1, al2, al3;
        uint32_t aoff = SWZ(a_base + kc * 32);
        LDSM_X4(ah0, ah1, ah2, ah3, sb + SM_A_HI + aoff);
        LDSM_X4(al0, al1, al2, al3, sb + SM_A_LO + aoff);

        uint32_t boff = SWZ(b_base + kc * 32);    // jp steps add 2048: swizzle-invariant
        #pragma unroll
        for (int jp = 0; jp < 9; ++jp) {
            uint32_t bh0, bh1, bh2, bh3, bl0, bl1, bl2, bl3;
            LDSM_X4(bh0, bh1, bh2, bh3, sb + SM_B_HI + boff);
            LDSM_X4(bl0, bl1, bl2, bl3, sb + SM_B_LO + boff);
            MMA16816(acc[2 * jp    ], ah0, ah1, ah2, ah3, bh0, bh1);
            MMA16816(acc[2 * jp + 1], ah0, ah1, ah2, ah3, bh2, bh3);
            MMA16816(acc[2 * jp    ], ah0, ah1, ah2, ah3, bl0, bl1);
            MMA16816(acc[2 * jp + 1], ah0, ah1, ah2, ah3, bl2, bl3);
            MMA16816(acc[2 * jp    ], al0, al1, al2, al3, bh0, bh1);
            MMA16816(acc[2 * jp + 1], al0, al1, al2, al3, bh2, bh3);
            boff += 16 * 128;
        }
    }

    __syncthreads();   // all warps done reading operand smem (band aliases B)

    // ---- epilogue: paired scatter into smem band tile (own rows only) ----
    // D frag: {d0,d1}=D[r0][c0,c0+1], {d2,d3}=D[r0+8][c0,c0+1]
    // band float index for (i, col): i*126 + col  (== i*127 + rr, rr = col - i)
    float* band = reinterpret_cast<float*>(smem + SM_BAND);
    {
        const int r0 = m0 + (lid >> 2);
        const int c0 = (lid & 3) * 2;
        #pragma unroll
        for (int j = 0; j < 18; ++j) {
            int n0 = m0 + j * 8;
            #pragma unroll
            for (int eh = 0; eh < 2; ++eh) {
                int i   = r0 + eh * 8;
                int col = n0 + c0;
                int idx = i * (R_OUT - 1) + col;
                unsigned rr = (unsigned)(col - i);
                float2 v = make_float2(acc[j][eh * 2], acc[j][eh * 2 + 1]);
                if (rr <= 125u) {
                    *reinterpret_cast<float2*>(band + idx) = v;     // STS.64
                } else if (rr == 126u) {
                    band[idx] = v.x;                                // last in-band col
                } else if (rr == 0xFFFFFFFFu) {
                    band[idx + 1] = v.y;                            // rr+1 == 0
                }
            }
        }
    }

    // ---- per-warp bulk store: warp w's 16 rows are a contiguous 8128B slice ----
    __syncwarp();
    if (lid == 0) {
        asm volatile("fence.proxy.async.shared::cta;" ::: "memory");
        float* dst = out + ((size_t)bh * T_LEN + t0) * R_OUT + m0 * R_OUT;
        uint32_t src = sb + SM_BAND + (uint32_t)(m0 * R_OUT * 4);
        asm volatile("cp.async.bulk.global.shared::cta.bulk_group [%0], [%1], %2;"
                     :: "l"(dst), "r"(src), "r"((uint32_t)(16 * R_OUT * 4)) : "memory");
        asm volatile("cp.async.bulk.commit_group;" ::: "memory");
        asm volatile("cp.async.bulk.wait_group.read 0;" ::: "memory");
    }
}

extern "C" void kernel_launch(void* const* d_in, const int* in_sizes, int n_in,
                              void* d_out, int out_size)
{
    const float* q = (const float*)d_in[0];
    const float* k = (const float*)d_in[1];
    float* out     = (float*)d_out;

    int bh = in_sizes[0] / (T_LEN * D_DIM);   // 128

    cudaFuncSetAttribute(unfold_dot_hmma,
                         cudaFuncAttributeMaxDynamicSharedMemorySize, SM_TOTAL);

    dim3 grid(T_LEN / TT, bh);
    unfold_dot_hmma<<<grid, 256, SM_TOTAL>>>(q, k, out);
}

// round 7
// speedup vs baseline: 1.6435x; 1.2396x over previous
#include <cuda_runtime.h>
#include <cuda_fp16.h>
#include <cstdint>

// Problem constants
#define T_LEN   4096
#define D_DIM   64
#define R_OUT   127
#define HALF_W  63

#define TT      128      // t rows per tile (M)
#define NS      256      // k halo rows staged (N); rows 254..255 zero
#define SROWS   254

// SMEM layout (fp16 tiles, 128 B per row, SW128-style 16B swizzle)
#define SM_A_HI   0
#define SM_A_LO   (SM_A_HI + TT * 128)      // 16384
#define SM_B      (SM_A_LO + TT * 128)      // 32768
#define SM_TOTAL  (SM_B + NS * 128)         // 65536
#define SM_BAND   0                          // aliased over A+B after compute (65024 B)

#define SWZ(off) ((off) ^ (((off) >> 3) & 0x70))

static __device__ __forceinline__ uint32_t smem_u32(const void* p) {
    uint32_t a;
    asm("{ .reg .u64 t; cvta.to.shared.u64 t, %1; cvt.u32.u64 %0, t; }" : "=r"(a) : "l"(p));
    return a;
}

// fp32x4 -> packed fp16x2 hi pair + fp16x2 residual lo pair
static __device__ __forceinline__ void split4h(float4 v, uint32_t& h0, uint32_t& h1,
                                               uint32_t& l0, uint32_t& l1) {
    __half2 a = __floats2half2_rn(v.x, v.y);
    __half2 b = __floats2half2_rn(v.z, v.w);
    float2 fa = __half22float2(a), fb = __half22float2(b);
    __half2 ra = __floats2half2_rn(v.x - fa.x, v.y - fa.y);
    __half2 rb = __floats2half2_rn(v.z - fb.x, v.w - fb.y);
    h0 = *reinterpret_cast<uint32_t*>(&a);
    h1 = *reinterpret_cast<uint32_t*>(&b);
    l0 = *reinterpret_cast<uint32_t*>(&ra);
    l1 = *reinterpret_cast<uint32_t*>(&rb);
}

// fp32x4 -> packed fp16x2 pair (round once, no residual)
static __device__ __forceinline__ void conv4h(float4 v, uint32_t& h0, uint32_t& h1) {
    __half2 a = __floats2half2_rn(v.x, v.y);
    __half2 b = __floats2half2_rn(v.z, v.w);
    h0 = *reinterpret_cast<uint32_t*>(&a);
    h1 = *reinterpret_cast<uint32_t*>(&b);
}

#define LDSM_X4(r0, r1, r2, r3, a) \
    asm volatile("ldmatrix.sync.aligned.m8n8.x4.shared.b16 {%0,%1,%2,%3}, [%4];" \
        : "=r"(r0), "=r"(r1), "=r"(r2), "=r"(r3) : "r"(a))

#define MMA16816(d, a0, a1, a2, a3, b0, b1) \
    asm volatile("mma.sync.aligned.m16n8k16.row.col.f32.f16.f16.f32 " \
        "{%0,%1,%2,%3}, {%4,%5,%6,%7}, {%8,%9}, {%0,%1,%2,%3};" \
        : "+f"(d[0]), "+f"(d[1]), "+f"(d[2]), "+f"(d[3]) \
        : "r"(a0), "r"(a1), "r"(a2), "r"(a3), "r"(b0), "r"(b1))

__global__ void __launch_bounds__(256, 2)
unfold_dot_hmma(const float* __restrict__ q,
                const float* __restrict__ k,
                float* __restrict__ out)
{
    extern __shared__ char smem[];
    const uint32_t sb = smem_u32(smem);
    const int tid = threadIdx.x;
    const int wid = tid >> 5;
    const int lid = tid & 31;
    const int t0  = blockIdx.x * TT;
    const int bh  = blockIdx.y;

    // ---- stage Q tile: 128 rows x 64 d -> fp16 hi/lo, swizzled rows of 128B ----
    const float4* qg = reinterpret_cast<const float4*>(q) +
                       ((size_t)bh * T_LEN + t0) * (D_DIM / 4);
    #pragma unroll
    for (int it = 0; it < 4; ++it) {
        int idx = tid + it * 256;          // 0..1023
        int row = idx >> 3;
        int g   = idx & 7;                 // 16B chunk within row
        float4 v0 = qg[row * 16 + g * 2];
        float4 v1 = qg[row * 16 + g * 2 + 1];
        uint32_t h0, h1, h2, h3, l0, l1, l2, l3;
        split4h(v0, h0, h1, l0, l1);
        split4h(v1, h2, h3, l2, l3);
        uint32_t off = SWZ((uint32_t)(row * 128 + g * 16));
        *reinterpret_cast<uint4*>(smem + SM_A_HI + off) = make_uint4(h0, h1, h2, h3);
        *reinterpret_cast<uint4*>(smem + SM_A_LO + off) = make_uint4(l0, l1, l2, l3);
    }

    // ---- stage K halo: 256 rows (s = t0-63+srow), fp16 hi only, zero-padded ----
    const float4* kg = reinterpret_cast<const float4*>(k) +
                       (size_t)bh * T_LEN * (D_DIM / 4);
    #pragma unroll
    for (int it = 0; it < 8; ++it) {
        int idx  = tid + it * 256;         // 0..2047
        int srow = idx >> 3;
        int g    = idx & 7;
        int sg   = t0 - HALF_W + srow;
        float4 v0 = make_float4(0.f, 0.f, 0.f, 0.f);
        float4 v1 = v0;
        if (srow < SROWS && (unsigned)sg < T_LEN) {
            v0 = kg[sg * 16 + g * 2];
            v1 = kg[sg * 16 + g * 2 + 1];
        }
        uint32_t h0, h1, h2, h3;
        conv4h(v0, h0, h1);
        conv4h(v1, h2, h3);
        uint32_t off = SWZ((uint32_t)(srow * 128 + g * 16));
        *reinterpret_cast<uint4*>(smem + SM_B + off) = make_uint4(h0, h1, h2, h3);
    }
    __syncthreads();

    // ---- compute: warp w owns rows [16w,16w+16), band col tiles j=0..17 at n0=m0+8j
    const int m0 = wid * 16;

    float acc[18][4];
    #pragma unroll
    for (int j = 0; j < 18; ++j)
        #pragma unroll
        for (int e = 0; e < 4; ++e) acc[j][e] = 0.f;

    // A lane address (ldmatrix x4)
    const int amat = lid >> 3;
    const uint32_t a_base = (uint32_t)((m0 + (amat & 1) * 8 + (lid & 7)) * 128
                                       + (amat >> 1) * 16);
    // B lane address (x4 over two adjacent n8 tiles)
    const int bg = lid >> 3;
    const uint32_t b_base = (uint32_t)((m0 + (bg >> 1) * 8 + (lid & 7)) * 128
                                       + (bg & 1) * 16);

    #pragma unroll
    for (int kc = 0; kc < 4; ++kc) {
        uint32_t ah0, ah1, ah2, ah3, al0, al1, al2, al3;
        uint32_t aoff = SWZ(a_base + kc * 32);
        LDSM_X4(ah0, ah1, ah2, ah3, sb + SM_A_HI + aoff);
        LDSM_X4(al0, al1, al2, al3, sb + SM_A_LO + aoff);

        uint32_t boff = SWZ(b_base + kc * 32);    // jp steps add 2048: swizzle-invariant
        #pragma unroll
        for (int jp = 0; jp < 9; ++jp) {
            uint32_t bh0, bh1, bh2, bh3;
            LDSM_X4(bh0, bh1, bh2, bh3, sb + SM_B + boff);
            // D = (Qh + Ql) * Kh  (fp16 2-product split)
            MMA16816(acc[2 * jp    ], ah0, ah1, ah2, ah3, bh0, bh1);
            MMA16816(acc[2 * jp + 1], ah0, ah1, ah2, ah3, bh2, bh3);
            MMA16816(acc[2 * jp    ], al0, al1, al2, al3, bh0, bh1);
            MMA16816(acc[2 * jp + 1], al0, al1, al2, al3, bh2, bh3);
            boff += 16 * 128;
        }
    }

    __syncthreads();   // all warps done reading operand smem (band aliases A+B)

    // ---- epilogue: paired scatter into smem band tile (own rows only) ----
    // D frag: {d0,d1}=D[r0][c0,c0+1], {d2,d3}=D[r0+8][c0,c0+1]
    // band float index for (i, col): i*126 + col  (== i*127 + rr, rr = col - i)
    float* band = reinterpret_cast<float*>(smem + SM_BAND);
    {
        const int r0 = m0 + (lid >> 2);
        const int c0 = (lid & 3) * 2;
        #pragma unroll
        for (int j = 0; j < 18; ++j) {
            int n0 = m0 + j * 8;
            #pragma unroll
            for (int eh = 0; eh < 2; ++eh) {
                int i   = r0 + eh * 8;
                int col = n0 + c0;
                int idx = i * (R_OUT - 1) + col;
                unsigned rr = (unsigned)(col - i);
                float2 v = make_float2(acc[j][eh * 2], acc[j][eh * 2 + 1]);
                if (rr <= 125u) {
                    *reinterpret_cast<float2*>(band + idx) = v;     // STS.64
                } else if (rr == 126u) {
                    band[idx] = v.x;                                // last in-band col
                } else if (rr == 0xFFFFFFFFu) {
                    band[idx + 1] = v.y;                            // rr+1 == 0
                }
            }
        }
    }

    // ---- per-warp bulk store: warp w's 16 rows are a contiguous 8128B slice ----
    __syncwarp();
    if (lid == 0) {
        asm volatile("fence.proxy.async.shared::cta;" ::: "memory");
        float* dst = out + ((size_t)bh * T_LEN + t0) * R_OUT + m0 * R_OUT;
        uint32_t src = sb + SM_BAND + (uint32_t)(m0 * R_OUT * 4);
        asm volatile("cp.async.bulk.global.shared::cta.bulk_group [%0], [%1], %2;"
                     :: "l"(dst), "r"(src), "r"((uint32_t)(16 * R_OUT * 4)) : "memory");
        asm volatile("cp.async.bulk.commit_group;" ::: "memory");
        asm volatile("cp.async.bulk.wait_group.read 0;" ::: "memory");
    }
}

extern "C" void kernel_launch(void* const* d_in, const int* in_sizes, int n_in,
                              void* d_out, int out_size)
{
    const float* q = (const float*)d_in[0];
    const float* k = (const float*)d_in[1];
    float* out     = (float*)d_out;

    int bh = in_sizes[0] / (T_LEN * D_DIM);   // 128

    cudaFuncSetAttribute(unfold_dot_hmma,
                         cudaFuncAttributeMaxDynamicSharedMemorySize, SM_TOTAL);

    dim3 grid(T_LEN / TT, bh);
    unfold_dot_hmma<<<grid, 256, SM_TOTAL>>>(q, k, out);
}

// round 8
// speedup vs baseline: 1.7717x; 1.0780x over previous
#include <cuda_runtime.h>
#include <cuda_fp16.h>
#include <cstdint>

// Problem constants
#define T_LEN   4096
#define D_DIM   64
#define R_OUT   127
#define HALF_W  63

#define TT      128      // t rows per tile (M)
#define NS      256      // k halo rows staged (N); rows 254..255 zero
#define SROWS   254

// SMEM layout (fp16 tiles, 128 B per row)
#define SM_A_HI   0
#define SM_A_LO   (SM_A_HI + TT * 128)      // 16384
#define SM_B      (SM_A_LO + TT * 128)      // 32768
#define SM_TOTAL  (SM_B + NS * 128)         // 65536
#define SM_BAND   0                          // aliased over A+B after compute (65024 B)

// standard SW128 swizzle (A tiles)
#define SWZ(off) ((off) ^ (((off) >> 3) & 0x70))

// custom B swizzle: 16B-chunk permutation keyed on row bits the column
// permutation varies: pchunk = chunk ^ (((row>>3)&3) | ((row&1)<<2))
static __device__ __forceinline__ uint32_t bswz(uint32_t row) {
    return ((row >> 3) & 3u) | ((row & 1u) << 2);
}

static __device__ __forceinline__ uint32_t smem_u32(const void* p) {
    uint32_t a;
    asm("{ .reg .u64 t; cvta.to.shared.u64 t, %1; cvt.u32.u64 %0, t; }" : "=r"(a) : "l"(p));
    return a;
}

// fp32x4 -> packed fp16x2 hi pair + fp16x2 residual lo pair
static __device__ __forceinline__ void split4h(float4 v, uint32_t& h0, uint32_t& h1,
                                               uint32_t& l0, uint32_t& l1) {
    __half2 a = __floats2half2_rn(v.x, v.y);
    __half2 b = __floats2half2_rn(v.z, v.w);
    float2 fa = __half22float2(a), fb = __half22float2(b);
    __half2 ra = __floats2half2_rn(v.x - fa.x, v.y - fa.y);
    __half2 rb = __floats2half2_rn(v.z - fb.x, v.w - fb.y);
    h0 = *reinterpret_cast<uint32_t*>(&a);
    h1 = *reinterpret_cast<uint32_t*>(&b);
    l0 = *reinterpret_cast<uint32_t*>(&ra);
    l1 = *reinterpret_cast<uint32_t*>(&rb);
}

// fp32x4 -> packed fp16x2 pair (round once)
static __device__ __forceinline__ void conv4h(float4 v, uint32_t& h0, uint32_t& h1) {
    __half2 a = __floats2half2_rn(v.x, v.y);
    __half2 b = __floats2half2_rn(v.z, v.w);
    h0 = *reinterpret_cast<uint32_t*>(&a);
    h1 = *reinterpret_cast<uint32_t*>(&b);
}

#define LDSM_X4(r0, r1, r2, r3, a) \
    asm volatile("ldmatrix.sync.aligned.m8n8.x4.shared.b16 {%0,%1,%2,%3}, [%4];" \
        : "=r"(r0), "=r"(r1), "=r"(r2), "=r"(r3) : "r"(a))

#define MMA16816(d, a0, a1, a2, a3, b0, b1) \
    asm volatile("mma.sync.aligned.m16n8k16.row.col.f32.f16.f16.f32 " \
        "{%0,%1,%2,%3}, {%4,%5,%6,%7}, {%8,%9}, {%0,%1,%2,%3};" \
        : "+f"(d[0]), "+f"(d[1]), "+f"(d[2]), "+f"(d[3]) \
        : "r"(a0), "r"(a1), "r"(a2), "r"(a3), "r"(b0), "r"(b1))

__global__ void __launch_bounds__(256, 2)
unfold_dot_hmma(const float* __restrict__ q,
                const float* __restrict__ k,
                float* __restrict__ out)
{
    extern __shared__ char smem[];
    const uint32_t sb = smem_u32(smem);
    const int tid = threadIdx.x;
    const int wid = tid >> 5;
    const int lid = tid & 31;
    const int t0  = blockIdx.x * TT;
    const int bh  = blockIdx.y;

    // ---- stage Q tile: 128 rows x 64 d -> fp16 hi/lo, standard SW128 ----
    const float4* qg = reinterpret_cast<const float4*>(q) +
                       ((size_t)bh * T_LEN + t0) * (D_DIM / 4);
    #pragma unroll
    for (int it = 0; it < 4; ++it) {
        int idx = tid + it * 256;          // 0..1023
        int row = idx >> 3;
        int g   = idx & 7;
        float4 v0 = qg[row * 16 + g * 2];
        float4 v1 = qg[row * 16 + g * 2 + 1];
        uint32_t h0, h1, h2, h3, l0, l1, l2, l3;
        split4h(v0, h0, h1, l0, l1);
        split4h(v1, h2, h3, l2, l3);
        uint32_t off = SWZ((uint32_t)(row * 128 + g * 16));
        *reinterpret_cast<uint4*>(smem + SM_A_HI + off) = make_uint4(h0, h1, h2, h3);
        *reinterpret_cast<uint4*>(smem + SM_A_LO + off) = make_uint4(l0, l1, l2, l3);
    }

    // ---- stage K halo: 256 rows, fp16, CUSTOM bswz chunk swizzle ----
    const float4* kg = reinterpret_cast<const float4*>(k) +
                       (size_t)bh * T_LEN * (D_DIM / 4);
    #pragma unroll
    for (int it = 0; it < 8; ++it) {
        int idx  = tid + it * 256;         // 0..2047
        int srow = idx >> 3;
        int g    = idx & 7;
        int sg   = t0 - HALF_W + srow;
        float4 v0 = make_float4(0.f, 0.f, 0.f, 0.f);
        float4 v1 = v0;
        if (srow < SROWS && (unsigned)sg < T_LEN) {
            v0 = kg[sg * 16 + g * 2];
            v1 = kg[sg * 16 + g * 2 + 1];
        }
        uint32_t h0, h1, h2, h3;
        conv4h(v0, h0, h1);
        conv4h(v1, h2, h3);
        uint32_t off = (uint32_t)(srow * 128) + (((uint32_t)g ^ bswz(srow)) << 4);
        *reinterpret_cast<uint4*>(smem + SM_B + off) = make_uint4(h0, h1, h2, h3);
    }
    __syncthreads();

    // ---- compute ----
    // Warp w: output rows [16w, 16w+16). Band cols [m0, m0+144) as 4 n32
    // super-tiles (s=0..3) of 4 column-permuted MMAs each + 1 leftover n16 pair.
    // MMA (s,p) computes real cols { m0+32s+8b+2p, +1 } for lane group b.
    const int m0 = wid * 16;

    float acc[18][4];
    #pragma unroll
    for (int j = 0; j < 18; ++j)
        #pragma unroll
        for (int e = 0; e < 4; ++e) acc[j][e] = 0.f;

    // A lane address (standard, unchanged)
    const int amat = lid >> 3;
    const uint32_t a_base = (uint32_t)((m0 + (amat & 1) * 8 + (lid & 7)) * 128
                                       + (amat >> 1) * 16);

    // B permuted lane constants: matrix m = lid>>3; khalf = m&1; phi = m>>1.
    // x4 #u of super-tile s: matrix rows = m0+32s + 8*(r>>1) + (r&1) + 2*(2u+phi)
    const int r7    = lid & 7;
    const int khalf = (lid >> 3) & 1;
    const int phi   = (lid >> 4) & 1;
    const uint32_t row0 = (uint32_t)(m0 + 8 * (r7 >> 1) + (r7 & 1) + 2 * phi);  // u=0
    const uint32_t row1 = row0 + 4;                                              // u=1
    const uint32_t swz0 = bswz(row0);
    const uint32_t swz1 = bswz(row1);
    // leftover n16 (cols m0+128..m0+143): rows = m0+128 + 4*(r>>1) + (r&1) + 2*phi
    const uint32_t rowL = (uint32_t)(m0 + 128 + 4 * (r7 >> 1) + (r7 & 1) + 2 * phi);
    const uint32_t swzL = bswz(rowL);

    #pragma unroll
    for (int kc = 0; kc < 4; ++kc) {
        uint32_t ah0, ah1, ah2, ah3, al0, al1, al2, al3;
        uint32_t aoff = SWZ(a_base + kc * 32);
        LDSM_X4(ah0, ah1, ah2, ah3, sb + SM_A_HI + aoff);
        LDSM_X4(al0, al1, al2, al3, sb + SM_A_LO + aoff);

        const uint32_t c0 = (uint32_t)(2 * kc + khalf);
        uint32_t ad0 = sb + SM_B + row0 * 128 + ((c0 ^ swz0) << 4);
        uint32_t ad1 = sb + SM_B + row1 * 128 + ((c0 ^ swz1) << 4);

        #pragma unroll
        for (int s = 0; s < 4; ++s) {
            uint32_t b0, b1, b2, b3;
            LDSM_X4(b0, b1, b2, b3, ad0);                 // MMAs p=0,1
            MMA16816(acc[4 * s + 0], ah0, ah1, ah2, ah3, b0, b1);
            MMA16816(acc[4 * s + 1], ah0, ah1, ah2, ah3, b2, b3);
            MMA16816(acc[4 * s + 0], al0, al1, al2, al3, b0, b1);
            MMA16816(acc[4 * s + 1], al0, al1, al2, al3, b2, b3);
            LDSM_X4(b0, b1, b2, b3, ad1);                 // MMAs p=2,3
            MMA16816(acc[4 * s + 2], ah0, ah1, ah2, ah3, b0, b1);
            MMA16816(acc[4 * s + 3], ah0, ah1, ah2, ah3, b2, b3);
            MMA16816(acc[4 * s + 2], al0, al1, al2, al3, b0, b1);
            MMA16816(acc[4 * s + 3], al0, al1, al2, al3, b2, b3);
            ad0 += 32 * 128;                               // +32 rows: swizzle-invariant
            ad1 += 32 * 128;
        }
        {   // leftover n16 pair (p=0,1)
            uint32_t b0, b1, b2, b3;
            uint32_t adL = sb + SM_B + rowL * 128 + ((c0 ^ swzL) << 4);
            LDSM_X4(b0, b1, b2, b3, adL);
            MMA16816(acc[16], ah0, ah1, ah2, ah3, b0, b1);
            MMA16816(acc[17], ah0, ah1, ah2, ah3, b2, b3);
            MMA16816(acc[16], al0, al1, al2, al3, b0, b1);
            MMA16816(acc[17], al0, al1, al2, al3, b2, b3);
        }
    }

    __syncthreads();   // all warps done reading operand smem (band aliases A+B)

    // ---- epilogue: conflict-free paired scatter into smem band tile ----
    // acc[4s+p]: lane (a=lid>>2, b=lid&3, eh) -> D[i=m0+a+8eh][col=m0+32s+8b+2p (+1)]
    // band float index: i*126 + col (== i*127 + rr, rr = col - i)
    float* band = reinterpret_cast<float*>(smem + SM_BAND);
    {
        const int i0 = m0 + (lid >> 2);
        const int cb = lid & 3;
        #pragma unroll
        for (int s = 0; s < 4; ++s) {
            #pragma unroll
            for (int p = 0; p < 4; ++p) {
                int col = m0 + 32 * s + 8 * cb + 2 * p;
                #pragma unroll
                for (int eh = 0; eh < 2; ++eh) {
                    int i   = i0 + 8 * eh;
                    int idx = i * (R_OUT - 1) + col;
                    unsigned rr = (unsigned)(col - i);
                    float2 v = make_float2(acc[4 * s + p][2 * eh],
                                           acc[4 * s + p][2 * eh + 1]);
                    if (rr <= 125u) {
                        *reinterpret_cast<float2*>(band + idx) = v;
                    } else if (rr == 126u) {
                        band[idx] = v.x;
                    } else if (rr == 0xFFFFFFFFu) {
                        band[idx + 1] = v.y;
                    }
                }
            }
        }
        #pragma unroll
        for (int p = 0; p < 2; ++p) {
            int col = m0 + 128 + 4 * cb + 2 * p;
            #pragma unroll
            for (int eh = 0; eh < 2; ++eh) {
                int i   = i0 + 8 * eh;
                int idx = i * (R_OUT - 1) + col;
                unsigned rr = (unsigned)(col - i);
                float2 v = make_float2(acc[16 + p][2 * eh],
                                       acc[16 + p][2 * eh + 1]);
                if (rr <= 125u) {
                    *reinterpret_cast<float2*>(band + idx) = v;
                } else if (rr == 126u) {
                    band[idx] = v.x;
                } else if (rr == 0xFFFFFFFFu) {
                    band[idx + 1] = v.y;
                }
            }
        }
    }

    // ---- per-warp bulk store: warp w's 16 rows are a contiguous 8128B slice ----
    __syncwarp();
    if (lid == 0) {
        asm volatile("fence.proxy.async.shared::cta;" ::: "memory");
        float* dst = out + ((size_t)bh * T_LEN + t0) * R_OUT + m0 * R_OUT;
        uint32_t src = sb + SM_BAND + (uint32_t)(m0 * R_OUT * 4);
        asm volatile("cp.async.bulk.global.shared::cta.bulk_group [%0], [%1], %2;"
                     :: "l"(dst), "r"(src), "r"((uint32_t)(16 * R_OUT * 4)) : "memory");
        asm volatile("cp.async.bulk.commit_group;" ::: "memory");
        asm volatile("cp.async.bulk.wait_group.read 0;" ::: "memory");
    }
}

extern "C" void kernel_launch(void* const* d_in, const int* in_sizes, int n_in,
                              void* d_out, int out_size)
{
    const float* q = (const float*)d_in[0];
    const float* k = (const float*)d_in[1];
    float* out     = (float*)d_out;

    int bh = in_sizes[0] / (T_LEN * D_DIM);   // 128

    cudaFuncSetAttribute(unfold_dot_hmma,
                         cudaFuncAttributeMaxDynamicSharedMemorySize, SM_TOTAL);

    dim3 grid(T_LEN / TT, bh);
    unfold_dot_hmma<<<grid, 256, SM_TOTAL>>>(q, k, out);
}